// round 1
// baseline (speedup 1.0000x reference)
#include <cuda_runtime.h>
#include <math.h>

// Problem constants (fixed shapes from the reference)
#define N_TOK 16384        // T*B = 2048*8
#define CDIM  512
#define ODIM  512
#define RDIM  64
#define NEXP  8
#define KTOT  4608         // (NEXP+1)*CDIM : 8 experts + bias matrix
#define TAUF  1.0f
#define COMMITF 0.1f

#define NBLK_A (N_TOK / 64)   // 256 gate blocks

// Scratch (device globals; no runtime allocation allowed)
__device__ float g_resp[N_TOK * NEXP];
__device__ float g_part[NBLK_A];

// ---------------------------------------------------------------------------
// Kernel A: GMM gate. Each block handles 64 tokens:
//   phase 1: k = x @ map_w^T + map_b   (64x64 output, K=512, tiled)
//   phase 2: distances -> log-resp -> softmax -> g_resp, per-block -sum(denom)
// ---------------------------------------------------------------------------
__global__ __launch_bounds__(256) void resp_kernel(
    const float* __restrict__ x,
    const float* __restrict__ map_w,
    const float* __restrict__ map_b,
    const float* __restrict__ cent,
    const float* __restrict__ prior)
{
    __shared__ float Xs[32][64];
    __shared__ float Ws[32][64];
    __shared__ float Ktile[64][65];
    __shared__ float red[64];

    const int tid = threadIdx.x;
    const int m0  = blockIdx.x * 64;
    const int ty  = tid >> 4;     // 0..15 -> token group
    const int tx  = tid & 15;     // 0..15 -> output-j group

    float acc[4][4];
#pragma unroll
    for (int i = 0; i < 4; ++i)
#pragma unroll
        for (int j = 0; j < 4; ++j) acc[i][j] = 0.0f;

    for (int k0 = 0; k0 < CDIM; k0 += 32) {
#pragma unroll
        for (int r = 0; r < 2; ++r) {
            int idx = tid + r * 256;        // 0..511
            int row = idx >> 3;             // 0..63
            int c4  = (idx & 7) << 2;       // 0,4,..,28
            float4 vx = *reinterpret_cast<const float4*>(
                &x[(size_t)(m0 + row) * CDIM + k0 + c4]);
            Xs[c4 + 0][row] = vx.x; Xs[c4 + 1][row] = vx.y;
            Xs[c4 + 2][row] = vx.z; Xs[c4 + 3][row] = vx.w;
            float4 vw = *reinterpret_cast<const float4*>(
                &map_w[(size_t)row * CDIM + k0 + c4]);
            Ws[c4 + 0][row] = vw.x; Ws[c4 + 1][row] = vw.y;
            Ws[c4 + 2][row] = vw.z; Ws[c4 + 3][row] = vw.w;
        }
        __syncthreads();
#pragma unroll
        for (int kk = 0; kk < 32; ++kk) {
            float a[4], b[4];
#pragma unroll
            for (int i = 0; i < 4; ++i) a[i] = Xs[kk][ty * 4 + i];
#pragma unroll
            for (int j = 0; j < 4; ++j) b[j] = Ws[kk][tx * 4 + j];
#pragma unroll
            for (int i = 0; i < 4; ++i)
#pragma unroll
                for (int j = 0; j < 4; ++j) acc[i][j] = fmaf(a[i], b[j], acc[i][j]);
        }
        __syncthreads();
    }

    // store k tile (+bias)
#pragma unroll
    for (int i = 0; i < 4; ++i)
#pragma unroll
        for (int j = 0; j < 4; ++j)
            Ktile[ty * 4 + i][tx * 4 + j] = acc[i][j] + map_b[tx * 4 + j];
    __syncthreads();

    float local = 0.0f;
    if (tid < 64) {
        const int tok = m0 + tid;
        float kk = 0.0f;
        float dot[NEXP], cc[NEXP];
#pragma unroll
        for (int e = 0; e < NEXP; ++e) { dot[e] = 0.0f; cc[e] = 0.0f; }
        for (int j = 0; j < RDIM; ++j) {
            float kv = Ktile[tid][j];
            kk = fmaf(kv, kv, kk);
#pragma unroll
            for (int e = 0; e < NEXP; ++e) {
                float ce = cent[e * RDIM + j];
                dot[e] = fmaf(kv, ce, dot[e]);
                cc[e]  = fmaf(ce, ce, cc[e]);
            }
        }
        const float CNST = 0.5f * (float)RDIM * logf(2.0f * 3.14159265358979323846f * TAUF);
        float lr[NEXP];
        float mx = -1e30f;
#pragma unroll
        for (int e = 0; e < NEXP; ++e) {
            float d2 = kk + cc[e] - 2.0f * dot[e];
            lr[e] = -0.5f * TAUF * d2 - CNST + logf(prior[e]);
            mx = fmaxf(mx, lr[e]);
        }
        float s = 0.0f;
#pragma unroll
        for (int e = 0; e < NEXP; ++e) s += expf(lr[e] - mx);
        float denom = mx + logf(s);
#pragma unroll
        for (int e = 0; e < NEXP; ++e)
            g_resp[(size_t)tok * NEXP + e] = expf(lr[e] - denom);
        local = -denom;
    }
    if (tid < 64) red[tid] = local;
    __syncthreads();
#pragma unroll
    for (int s2 = 32; s2 > 0; s2 >>= 1) {
        if (tid < s2) red[tid] += red[tid + s2];
        __syncthreads();
    }
    if (tid == 0) g_part[blockIdx.x] = red[0];
}

// ---------------------------------------------------------------------------
// Loss reducer: deterministic tree over 256 block partials.
// ---------------------------------------------------------------------------
__global__ void loss_kernel(float* __restrict__ out, size_t loss_idx)
{
    __shared__ float red[256];
    int t = threadIdx.x;
    red[t] = (t < NBLK_A) ? g_part[t] : 0.0f;
    __syncthreads();
#pragma unroll
    for (int s = 128; s > 0; s >>= 1) {
        if (t < s) red[t] += red[t + s];
        __syncthreads();
    }
    if (t == 0) out[loss_idx] = COMMITF * red[0];
}

// ---------------------------------------------------------------------------
// Kernel B: the fused mixture GEMM.
//   y[n,o] = sum_{e=0..8} s(n,e) * sum_i x[n,i] * Wg_e[o,i] + bias_b[o]
// where s(n,e)=resp[n,e] for e<8, 1 for e=8 (bias_w group).
// Single NT-GEMM: M=16384, N=512, K=4608. A generated on the fly (x scaled by
// resp during the A-tile load). 128x128x16 tile, 256 threads, 8x8 micro.
// ---------------------------------------------------------------------------
#define BM 128
#define BN 128
#define BK 16

__global__ __launch_bounds__(256) void moe_gemm(
    const float* __restrict__ x,
    const float* __restrict__ pw_w,
    const float* __restrict__ bias_w,
    const float* __restrict__ bias_b,
    float* __restrict__ out)
{
    __shared__ float As[BK][BM];
    __shared__ float Bs[BK][BN];

    const int tid = threadIdx.x;
    const int m0  = blockIdx.y * BM;
    const int n0  = blockIdx.x * BN;
    const int tx  = tid & 15;     // col group
    const int ty  = tid >> 4;     // row group

    float acc[8][8];
#pragma unroll
    for (int i = 0; i < 8; ++i)
#pragma unroll
        for (int j = 0; j < 8; ++j) acc[i][j] = 0.0f;

    for (int k0 = 0; k0 < KTOT; k0 += BK) {
        const int e  = k0 >> 9;          // 0..8 (constant within tile: 512%16==0)
        const int i0 = k0 & 511;
        const float* bsrc = (e < NEXP) ? (pw_w + (size_t)e * ODIM * CDIM) : bias_w;

#pragma unroll
        for (int r = 0; r < 2; ++r) {
            int idx = tid + r * 256;          // 0..511
            int row = idx >> 2;               // 0..127
            int c4  = (idx & 3) << 2;         // 0,4,8,12
            // A tile: x scaled by responsibility (1.0 for the bias group)
            int gm = m0 + row;
            float sc = (e < NEXP) ? __ldg(&g_resp[(size_t)gm * NEXP + e]) : 1.0f;
            float4 va = *reinterpret_cast<const float4*>(
                &x[(size_t)gm * CDIM + i0 + c4]);
            As[c4 + 0][row] = va.x * sc; As[c4 + 1][row] = va.y * sc;
            As[c4 + 2][row] = va.z * sc; As[c4 + 3][row] = va.w * sc;
            // B tile
            int go = n0 + row;
            float4 vb = *reinterpret_cast<const float4*>(
                &bsrc[(size_t)go * CDIM + i0 + c4]);
            Bs[c4 + 0][row] = vb.x; Bs[c4 + 1][row] = vb.y;
            Bs[c4 + 2][row] = vb.z; Bs[c4 + 3][row] = vb.w;
        }
        __syncthreads();

#pragma unroll
        for (int kk = 0; kk < BK; ++kk) {
            float a[8], b[8];
            *reinterpret_cast<float4*>(&a[0]) =
                *reinterpret_cast<const float4*>(&As[kk][ty * 8 + 0]);
            *reinterpret_cast<float4*>(&a[4]) =
                *reinterpret_cast<const float4*>(&As[kk][ty * 8 + 4]);
            *reinterpret_cast<float4*>(&b[0]) =
                *reinterpret_cast<const float4*>(&Bs[kk][tx * 8 + 0]);
            *reinterpret_cast<float4*>(&b[4]) =
                *reinterpret_cast<const float4*>(&Bs[kk][tx * 8 + 4]);
#pragma unroll
            for (int i = 0; i < 8; ++i)
#pragma unroll
                for (int j = 0; j < 8; ++j)
                    acc[i][j] = fmaf(a[i], b[j], acc[i][j]);
        }
        __syncthreads();
    }

    // epilogue: + bias_b, vectorized store
    float bb[8];
    *reinterpret_cast<float4*>(&bb[0]) =
        *reinterpret_cast<const float4*>(&bias_b[n0 + tx * 8 + 0]);
    *reinterpret_cast<float4*>(&bb[4]) =
        *reinterpret_cast<const float4*>(&bias_b[n0 + tx * 8 + 4]);
#pragma unroll
    for (int i = 0; i < 8; ++i) {
        size_t base = (size_t)(m0 + ty * 8 + i) * ODIM + n0 + tx * 8;
        float4 v0 = make_float4(acc[i][0] + bb[0], acc[i][1] + bb[1],
                                acc[i][2] + bb[2], acc[i][3] + bb[3]);
        float4 v1 = make_float4(acc[i][4] + bb[4], acc[i][5] + bb[5],
                                acc[i][6] + bb[6], acc[i][7] + bb[7]);
        *reinterpret_cast<float4*>(&out[base + 0]) = v0;
        *reinterpret_cast<float4*>(&out[base + 4]) = v1;
    }
}

// ---------------------------------------------------------------------------
extern "C" void kernel_launch(void* const* d_in, const int* in_sizes, int n_in,
                              void* d_out, int out_size)
{
    const float* x      = (const float*)d_in[0];
    // d_in[1] = key_feat (ignored by the forward)
    const float* map_w  = (const float*)d_in[2];
    const float* map_b  = (const float*)d_in[3];
    const float* cent   = (const float*)d_in[4];
    const float* prior  = (const float*)d_in[5];
    const float* pw_w   = (const float*)d_in[6];
    const float* bias_w = (const float*)d_in[7];
    const float* bias_b = (const float*)d_in[8];
    float* out = (float*)d_out;

    // 1) gate: responsibilities + per-block loss partials
    resp_kernel<<<NBLK_A, 256>>>(x, map_w, map_b, cent, prior);
    // 2) deterministic loss reduction -> out[out_size-1]
    loss_kernel<<<1, 256>>>(out, (size_t)out_size - 1);
    // 3) fused mixture GEMM -> out[0 .. N*O)
    dim3 grid(ODIM / BN, N_TOK / BM);
    moe_gemm<<<grid, 256>>>(x, pw_w, bias_w, bias_b, out);
}